// round 5
// baseline (speedup 1.0000x reference)
#include <cuda_runtime.h>
#include <cuda_fp16.h>

#define NUM_SEG 512
#define D 64
#define D4 (D / 4)     // 16 float4 chunks per row
#define QPS 4          // quarter-blocks per segment in stats

// Scratch (device globals; fully overwritten every call -> deterministic, graph-safe).
// g_xh: fp16 shadow of x, 4 halves per uint2 -> N*16 entries (128 MB for N=1e6).
__device__ uint2  g_xh[16777216];
__device__ float4 g_psum[NUM_SEG * QPS * D4];
__device__ float  g_psq [NUM_SEG * QPS];
__device__ float4 g_mean[NUM_SEG * D4];
__device__ float  g_inv [NUM_SEG];

__device__ __forceinline__ int lower_bound_i32(const int* __restrict__ a, int n, int v) {
    int lo = 0, hi = n;
    while (lo < hi) {
        int mid = (lo + hi) >> 1;
        if (a[mid] < v) lo = mid + 1; else hi = mid;
    }
    return lo;
}

__device__ __forceinline__ uint2 f4_to_h4(float4 v) {
    __half2 lo = __float22half2_rn(make_float2(v.x, v.y));
    __half2 hi = __float22half2_rn(make_float2(v.z, v.w));
    uint2 r;
    r.x = *(unsigned int*)&lo;
    r.y = *(unsigned int*)&hi;
    return r;
}

__device__ __forceinline__ float4 h4_to_f4(uint2 h) {
    __half2 lo = *(__half2*)&h.x;
    __half2 hi = *(__half2*)&h.y;
    float2 a = __half22float2(lo);
    float2 b = __half22float2(hi);
    return make_float4(a.x, a.y, b.x, b.y);
}

// K1: partial stats + fp16 shadow copy. Block = (segment s, quarter q).
__global__ __launch_bounds__(256) void k_stats(
    const float4* __restrict__ x4,   // [N,16] float4 view
    const int* __restrict__ batch,   // [N] sorted int32
    int N)
{
    const int bid = blockIdx.x;
    const int s   = bid >> 2;
    const int q   = bid & 3;
    const int tid = threadIdx.x;

    __shared__ int sh_lo, sh_hi;
    if (tid == 0)  sh_lo = lower_bound_i32(batch, N, s);
    if (tid == 32) sh_hi = lower_bound_i32(batch, N, s + 1);
    __syncthreads();
    const int lo = sh_lo, hi = sh_hi;
    const int len = hi - lo;
    const int qlo = lo + ((len * q) >> 2);
    const int qhi = lo + ((len * (q + 1)) >> 2);

    const int c4 = tid & (D4 - 1);  // column chunk 0..15
    const int rg = tid >> 4;        // row group 0..15

    float4 sum4 = make_float4(0.f, 0.f, 0.f, 0.f);
    float  sq   = 0.f;
    int r = qlo + rg;
    for (; r + 16 < qhi; r += 32) {
        const size_t i0 = (size_t)r * D4 + c4;
        const size_t i1 = (size_t)(r + 16) * D4 + c4;
        float4 v0 = __ldcs(&x4[i0]);   // evict-first: x never re-read from fp32
        float4 v1 = __ldcs(&x4[i1]);
        g_xh[i0] = f4_to_h4(v0);       // default policy: keep resident in L2
        g_xh[i1] = f4_to_h4(v1);
        sum4.x += v0.x + v1.x; sum4.y += v0.y + v1.y;
        sum4.z += v0.z + v1.z; sum4.w += v0.w + v1.w;
        sq += v0.x * v0.x + v0.y * v0.y + v0.z * v0.z + v0.w * v0.w;
        sq += v1.x * v1.x + v1.y * v1.y + v1.z * v1.z + v1.w * v1.w;
    }
    if (r < qhi) {
        const size_t i0 = (size_t)r * D4 + c4;
        float4 v0 = __ldcs(&x4[i0]);
        g_xh[i0] = f4_to_h4(v0);
        sum4.x += v0.x; sum4.y += v0.y; sum4.z += v0.z; sum4.w += v0.w;
        sq += v0.x * v0.x + v0.y * v0.y + v0.z * v0.z + v0.w * v0.w;
    }

    __shared__ float4 ssum[256];
    __shared__ float  ssq[256];
    ssum[tid] = sum4;
    ssq[tid]  = sq;
    __syncthreads();
    for (int off = 128; off >= D4; off >>= 1) {
        if (tid < off) {
            float4 a = ssum[tid], b = ssum[tid + off];
            a.x += b.x; a.y += b.y; a.z += b.z; a.w += b.w;
            ssum[tid] = a;
            ssq[tid] += ssq[tid + off];
        }
        __syncthreads();
    }
    if (tid < D4) g_psum[bid * D4 + tid] = ssum[tid];
    if (tid == 0) {
        float t = 0.f;
#pragma unroll
        for (int i = 0; i < D4; i++) t += ssq[i];
        g_psq[bid] = t;
    }
}

// K2: finalize. Block = segment, 32 threads.
__global__ __launch_bounds__(32) void k_finalize(
    const int* __restrict__ batch, int N)
{
    const int s = blockIdx.x;
    const int t = threadIdx.x;

    const int lo = lower_bound_i32(batch, N, s);
    const int hi = lower_bound_i32(batch, N, s + 1);
    const float invc = 1.f / (float)max(hi - lo, 1);

    float msq = 0.f;
    if (t < D4) {
        float4 a = g_psum[(s * QPS + 0) * D4 + t];
        float4 b = g_psum[(s * QPS + 1) * D4 + t];
        float4 c = g_psum[(s * QPS + 2) * D4 + t];
        float4 d = g_psum[(s * QPS + 3) * D4 + t];
        float4 m;
        m.x = (a.x + b.x + c.x + d.x) * invc;
        m.y = (a.y + b.y + c.y + d.y) * invc;
        m.z = (a.z + b.z + c.z + d.z) * invc;
        m.w = (a.w + b.w + c.w + d.w) * invc;
        g_mean[s * D4 + t] = m;
        msq = m.x * m.x + m.y * m.y + m.z * m.z + m.w * m.w;
    }
#pragma unroll
    for (int off = 8; off >= 1; off >>= 1)
        msq += __shfl_down_sync(0xffffffffu, msq, off);
    if (t == 0) {
        float sq_tot = g_psq[s * QPS + 0] + g_psq[s * QPS + 1]
                     + g_psq[s * QPS + 2] + g_psq[s * QPS + 3];
        // segment_mean(|x-m|^2) = segment_mean(|x|^2) - |m|^2
        float var = sq_tot * invc - msq;
        g_inv[s] = rsqrtf(var);
    }
}

// K3: apply from the (mostly L2-resident) fp16 shadow; streaming fp32 output.
__global__ __launch_bounds__(256) void k_apply(
    const int* __restrict__ batch,
    float4* __restrict__ out4,
    int total4)
{
    const int idx = blockIdx.x * blockDim.x + threadIdx.x;
    if (idx >= total4) return;
    const int row = idx >> 4;
    const int c4  = idx & (D4 - 1);
    int s = batch[row];
    s = min(max(s, 0), NUM_SEG - 1);

    uint2 h = __ldcs(&g_xh[idx]);    // dead after read -> evict-first
    float4 v = h4_to_f4(h);
    const float4 m = g_mean[s * D4 + c4];
    const float  g = g_inv[s];

    float4 o;
    o.x = (v.x - m.x) * g;
    o.y = (v.y - m.y) * g;
    o.z = (v.z - m.z) * g;
    o.w = (v.w - m.w) * g;
    __stcs(&out4[idx], o);           // streaming store: don't evict the shadow
}

extern "C" void kernel_launch(void* const* d_in, const int* in_sizes, int n_in,
                              void* d_out, int out_size)
{
    const float* x     = (const float*)d_in[0];   // [N, 64]
    const int*   batch = (const int*)d_in[1];     // [N], sorted int32
    float*       out   = (float*)d_out;

    const int N = in_sizes[1];
    const float4* x4   = (const float4*)x;
    float4*       out4 = (float4*)out;

    k_stats<<<NUM_SEG * QPS, 256>>>(x4, batch, N);
    k_finalize<<<NUM_SEG, 32>>>(batch, N);

    const int total4 = N * D4;
    const int blocks = (total4 + 255) / 256;
    k_apply<<<blocks, 256>>>(batch, out4, total4);
}

// round 7
// speedup vs baseline: 1.1837x; 1.1837x over previous
#include <cuda_runtime.h>
#include <cuda_fp16.h>

#define NUM_SEG 512
#define D4 16          // float4 chunks per row (D=64)
#define CPS 16         // chunks per segment
#define TPB 256
#define CAP 144        // max rows cached in smem per chunk (covers len <= 2304)

// Device scratch (overwritten/reset every launch -> deterministic).
__device__ float4 g_psum[NUM_SEG * CPS * D4];
__device__ float  g_psq [NUM_SEG * CPS];
__device__ float4 g_mean[NUM_SEG * D4];
__device__ float  g_inv [NUM_SEG];
__device__ int    g_cnt [NUM_SEG];
__device__ int    g_flag[NUM_SEG];

__device__ __forceinline__ int lower_bound_i32(const int* __restrict__ a, int n, int v) {
    int lo = 0, hi = n;
    while (lo < hi) {
        int mid = (lo + hi) >> 1;
        if (a[mid] < v) lo = mid + 1; else hi = mid;
    }
    return lo;
}

__device__ __forceinline__ uint2 f4_to_h4(float4 v) {
    __half2 lo = __float22half2_rn(make_float2(v.x, v.y));
    __half2 hi = __float22half2_rn(make_float2(v.z, v.w));
    uint2 r;
    r.x = *(unsigned int*)&lo;
    r.y = *(unsigned int*)&hi;
    return r;
}
__device__ __forceinline__ float4 h4_to_f4(uint2 h) {
    float2 a = __half22float2(*(__half2*)&h.x);
    float2 b = __half22float2(*(__half2*)&h.y);
    return make_float4(a.x, a.y, b.x, b.y);
}

__global__ __launch_bounds__(32) void k_init() {
    g_cnt[threadIdx.x * 16 + blockIdx.x] = 0;   // any full cover works; see launch
    g_flag[threadIdx.x * 16 + blockIdx.x] = 0;
}

__global__ __launch_bounds__(TPB) void k_fused(
    const float4* __restrict__ x4,   // [N,16]
    const int* __restrict__ batch,   // [N] sorted int32
    float4* __restrict__ out4,
    int N)
{
    const int bid = blockIdx.x;
    const int s   = bid >> 4;        // segment
    const int q   = bid & 15;        // chunk within segment
    const int tid = threadIdx.x;
    const int lane = tid & 31;
    const int wid  = tid >> 5;       // 0..7
    const int c4 = tid & (D4 - 1);   // column chunk 0..15
    const int rg = tid >> 4;         // row group 0..15

    __shared__ uint2  sh_x[CAP * D4];          // fp16 chunk cache (18.4 KB)
    __shared__ float4 sh_wsum[8 * D4];
    __shared__ float  sh_wsq[8];
    __shared__ float  sh_msq[D4];
    __shared__ int    sh_lo, sh_hi, sh_last;

    if (tid == 0)  sh_lo = lower_bound_i32(batch, N, s);
    if (tid == 32) sh_hi = lower_bound_i32(batch, N, s + 1);
    __syncthreads();
    const int lo = sh_lo, hi = sh_hi;
    const int len = hi - lo;
    const int qlo = lo + ((len * q) >> 4);
    const int qhi = lo + ((len * (q + 1)) >> 4);
    const int nrows = qhi - qlo;

    // ---- Phase A: stream-read chunk, accumulate, cache fp16 in smem ----
    float4 sum4 = make_float4(0.f, 0.f, 0.f, 0.f);
    float  sq   = 0.f;
#pragma unroll 2
    for (int rr = rg; rr < nrows; rr += 16) {
        float4 v = __ldcs(&x4[(size_t)(qlo + rr) * D4 + c4]);
        sum4.x += v.x; sum4.y += v.y; sum4.z += v.z; sum4.w += v.w;
        sq += v.x * v.x + v.y * v.y + v.z * v.z + v.w * v.w;
        if (rr < CAP) sh_x[rr * D4 + c4] = f4_to_h4(v);
    }

    // warp reduce: +16 lane combines the two row-groups sharing c4
    const unsigned FULL = 0xffffffffu;
    sum4.x += __shfl_down_sync(FULL, sum4.x, 16);
    sum4.y += __shfl_down_sync(FULL, sum4.y, 16);
    sum4.z += __shfl_down_sync(FULL, sum4.z, 16);
    sum4.w += __shfl_down_sync(FULL, sum4.w, 16);
#pragma unroll
    for (int off = 16; off >= 1; off >>= 1)
        sq += __shfl_down_sync(FULL, sq, off);
    if (lane < D4) sh_wsum[wid * D4 + lane] = sum4;
    if (lane == 0) sh_wsq[wid] = sq;
    __syncthreads();

    if (tid < D4) {
        float4 t = sh_wsum[tid];
#pragma unroll
        for (int w = 1; w < 8; w++) {
            float4 b = sh_wsum[w * D4 + tid];
            t.x += b.x; t.y += b.y; t.z += b.z; t.w += b.w;
        }
        g_psum[bid * D4 + tid] = t;
    }
    if (tid == 0) {
        float t = 0.f;
#pragma unroll
        for (int w = 0; w < 8; w++) t += sh_wsq[w];
        g_psq[bid] = t;
    }
    __threadfence();
    __syncthreads();
    if (tid == 0) sh_last = (atomicAdd(&g_cnt[s], 1) == CPS - 1);
    __syncthreads();

    const float invc = 1.f / (float)max(len, 1);

    if (sh_last) {
        // ---- Finalize (this block is the 16th arriver for segment s) ----
        float4 p = __ldcg(&g_psum[s * (CPS * D4) + tid]);  // tid = qq*16 + c4
        p.x += __shfl_down_sync(FULL, p.x, 16);
        p.y += __shfl_down_sync(FULL, p.y, 16);
        p.z += __shfl_down_sync(FULL, p.z, 16);
        p.w += __shfl_down_sync(FULL, p.w, 16);
        if (lane < D4) sh_wsum[wid * D4 + lane] = p;
        __syncthreads();
        if (tid < D4) {
            float4 t = sh_wsum[tid];
#pragma unroll
            for (int w = 1; w < 8; w++) {
                float4 b = sh_wsum[w * D4 + tid];
                t.x += b.x; t.y += b.y; t.z += b.z; t.w += b.w;
            }
            float4 m = make_float4(t.x * invc, t.y * invc, t.z * invc, t.w * invc);
            g_mean[s * D4 + tid] = m;
            sh_msq[tid] = m.x * m.x + m.y * m.y + m.z * m.z + m.w * m.w;
        }
        __syncthreads();
        if (tid == 0) {
            float sq_tot = 0.f, msq = 0.f;
#pragma unroll
            for (int i = 0; i < CPS; i++) sq_tot += __ldcg(&g_psq[s * CPS + i]);
#pragma unroll
            for (int i = 0; i < D4; i++) msq += sh_msq[i];
            // segment_mean(|x-m|^2) = segment_mean(|x|^2) - |m|^2
            float var = sq_tot * invc - msq;
            g_inv[s] = rsqrtf(var);
            __threadfence();
            atomicExch(&g_flag[s], 1);
        }
        __syncthreads();
    } else {
        // ---- Wait for segment finalize ----
        if (tid == 0) {
            while (((volatile int*)g_flag)[s] == 0) __nanosleep(128);
        }
        __syncthreads();
        __threadfence();
    }

    // ---- Phase B: apply from smem fp16 cache, streaming fp32 output ----
    const float4 m  = __ldcg(&g_mean[s * D4 + c4]);
    const float  gi = __ldcg(&g_inv[s]);

#pragma unroll 2
    for (int rr = rg; rr < nrows; rr += 16) {
        const size_t idx = (size_t)(qlo + rr) * D4 + c4;
        float4 v;
        if (rr < CAP) v = h4_to_f4(sh_x[rr * D4 + c4]);
        else          v = __ldcg(&x4[idx]);   // fallback (chunk > CAP rows: ~never)
        float4 o;
        o.x = (v.x - m.x) * gi;
        o.y = (v.y - m.y) * gi;
        o.z = (v.z - m.z) * gi;
        o.w = (v.w - m.w) * gi;
        __stcs(&out4[idx], o);
    }
}

extern "C" void kernel_launch(void* const* d_in, const int* in_sizes, int n_in,
                              void* d_out, int out_size)
{
    const float* x     = (const float*)d_in[0];   // [N, 64]
    const int*   batch = (const int*)d_in[1];     // [N], sorted int32
    float*       out   = (float*)d_out;
    const int N = in_sizes[1];

    k_init<<<16, 32>>>();   // 16*32 = 512 counters + flags
    k_fused<<<NUM_SEG * CPS, TPB>>>((const float4*)x, batch, (float4*)out, N);
}